// round 6
// baseline (speedup 1.0000x reference)
#include <cuda_runtime.h>
#include <mma.h>
using namespace nvcuda;

#define NS 512
#define NR 384
#define CM 256
#define MT (NR*32)       // 12288
#define RT (NR*NR)       // 147456

__device__ float g_L[(size_t)NS * MT];
__device__ float g_R[(size_t)NS * MT];
__device__ float g_inter[(size_t)RT * 1024];
__device__ float g_rinv[RT];

// ---------------- Kernel 1: LN + left/right projection (fp32 exact) --------
__global__ __launch_bounds__(256) void ln_proj_kernel(
    const float* __restrict__ act, const float* __restrict__ mask,
    const float* __restrict__ gamma, const float* __restrict__ beta,
    const float* __restrict__ lw, const float* __restrict__ lb,
    const float* __restrict__ rw, const float* __restrict__ rb)
{
    extern __shared__ float sm[];
    float* xs    = sm;                 // [64][260]
    float* sW    = sm + 64 * 260;      // [256][64]
    float* smask = sW + 256 * 64;      // [64]
    const int tid  = threadIdx.x;
    const int warp = tid >> 5, lane = tid & 31;
    const int rbase = blockIdx.x * 64;

    for (int i = 0; i < 64; i++) {
        int idx = tid + i * 256;
        int k = idx >> 6, cc = idx & 63;
        sW[idx] = (cc < 32) ? lw[k * 32 + cc] : rw[k * 32 + (cc - 32)];
    }
    for (int rr = 0; rr < 8; rr++) {
        int lr = warp * 8 + rr;
        int r  = rbase + lr;
        const float* arow = act + (size_t)r * CM;
        float x[8], s = 0.f, s2 = 0.f;
        #pragma unroll
        for (int j = 0; j < 8; j++) { x[j] = arow[lane + 32 * j]; s += x[j]; s2 += x[j] * x[j]; }
        #pragma unroll
        for (int o = 16; o > 0; o >>= 1) {
            s  += __shfl_xor_sync(0xffffffffu, s,  o);
            s2 += __shfl_xor_sync(0xffffffffu, s2, o);
        }
        float mu = s * (1.f / 256.f);
        float rstd = rsqrtf(s2 * (1.f / 256.f) - mu * mu + 1e-5f);
        float m = mask[r];
        if (lane == 0) smask[lr] = m;
        #pragma unroll
        for (int j = 0; j < 8; j++) {
            int k = lane + 32 * j;
            xs[lr * 260 + k] = ((x[j] - mu) * rstd * gamma[k] + beta[k]) * m;
        }
    }
    __syncthreads();

    const int tr4 = (tid >> 4) * 4, tc4 = (tid & 15) * 4;
    float acc[4][4] = {};
    for (int k = 0; k < 256; k += 4) {
        float4 w0 = *(const float4*)(sW + (k + 0) * 64 + tc4);
        float4 w1 = *(const float4*)(sW + (k + 1) * 64 + tc4);
        float4 w2 = *(const float4*)(sW + (k + 2) * 64 + tc4);
        float4 w3 = *(const float4*)(sW + (k + 3) * 64 + tc4);
        #pragma unroll
        for (int i = 0; i < 4; i++) {
            float4 xv = *(const float4*)(xs + (tr4 + i) * 260 + k);
            acc[i][0] += xv.x * w0.x + xv.y * w1.x + xv.z * w2.x + xv.w * w3.x;
            acc[i][1] += xv.x * w0.y + xv.y * w1.y + xv.z * w2.y + xv.w * w3.y;
            acc[i][2] += xv.x * w0.z + xv.y * w1.z + xv.z * w2.z + xv.w * w3.z;
            acc[i][3] += xv.x * w0.w + xv.y * w1.w + xv.z * w2.w + xv.w * w3.w;
        }
    }
    float b0, b1, b2, b3;
    if (tc4 < 32) { b0 = lb[tc4]; b1 = lb[tc4+1]; b2 = lb[tc4+2]; b3 = lb[tc4+3]; }
    else { b0 = rb[tc4-32]; b1 = rb[tc4-31]; b2 = rb[tc4-30]; b3 = rb[tc4-29]; }
    #pragma unroll
    for (int i = 0; i < 4; i++) {
        int r = rbase + tr4 + i;
        int aa = r / NR, bb = r % NR;
        float m = smask[tr4 + i];
        float4 o = { acc[i][0] + m * b0, acc[i][1] + m * b1,
                     acc[i][2] + m * b2, acc[i][3] + m * b3 };
        if (tc4 < 32) *(float4*)(g_L + (size_t)aa * MT + bb * 32 + tc4) = o;
        else          *(float4*)(g_R + (size_t)aa * MT + bb * 32 + (tc4 - 32)) = o;
    }
}

// ---------------- Kernel 2: rinv = 1/(eps + mask^T mask) -------------------
__global__ __launch_bounds__(NR) void norm_kernel(const float* __restrict__ mask)
{
    int b = blockIdx.x, d = threadIdx.x;
    float s = 0.f;
    for (int a = 0; a < NS; a++) s += mask[a * NR + b] * mask[a * NR + d];
    g_rinv[b * NR + d] = 1.f / (1e-3f + s);
}

// ---------------- Kernel 3: inter = L^T R (tf32 wmma) ----------------------
__global__ __launch_bounds__(256) void gemm1_kernel()
{
    extern __shared__ float sm[];
    float* sA = sm;              // [32][132]
    float* sB = sm + 32 * 132;   // [32][260]
    const int tid  = threadIdx.x;
    const int warp = tid >> 5;
    const int wm = warp >> 2, wn = warp & 3;   // 2x4 warp grid of 64x64 slabs
    const int m0 = blockIdx.y * 128, n0 = blockIdx.x * 256;

    wmma::fragment<wmma::accumulator, 16, 16, 8, float> c[4][4];
    #pragma unroll
    for (int i = 0; i < 4; i++)
        #pragma unroll
        for (int j = 0; j < 4; j++) wmma::fill_fragment(c[i][j], 0.0f);

    for (int k0 = 0; k0 < NS; k0 += 32) {
        #pragma unroll
        for (int i = 0; i < 4; i++) {
            int idx = tid + i * 256;                    // 1024 float4s
            int kk = idx >> 5, c4 = (idx & 31) << 2;
            *(float4*)(sA + kk * 132 + c4) =
                *(const float4*)(g_L + (size_t)(k0 + kk) * MT + m0 + c4);
        }
        #pragma unroll
        for (int i = 0; i < 8; i++) {
            int idx = tid + i * 256;                    // 2048 float4s
            int kk = idx >> 6, c4 = (idx & 63) << 2;
            *(float4*)(sB + kk * 260 + c4) =
                *(const float4*)(g_R + (size_t)(k0 + kk) * MT + n0 + c4);
        }
        __syncthreads();
        #pragma unroll
        for (int kk = 0; kk < 32; kk += 8) {
            wmma::fragment<wmma::matrix_a, 16, 16, 8, wmma::precision::tf32, wmma::col_major> af[4];
            wmma::fragment<wmma::matrix_b, 16, 16, 8, wmma::precision::tf32, wmma::row_major> bf[4];
            #pragma unroll
            for (int i = 0; i < 4; i++) {
                wmma::load_matrix_sync(af[i], sA + kk * 132 + wm * 64 + i * 16, 132);
                #pragma unroll
                for (int t = 0; t < af[i].num_elements; t++)
                    af[i].x[t] = wmma::__float_to_tf32(af[i].x[t]);
            }
            #pragma unroll
            for (int j = 0; j < 4; j++) {
                wmma::load_matrix_sync(bf[j], sB + kk * 260 + wn * 64 + j * 16, 260);
                #pragma unroll
                for (int t = 0; t < bf[j].num_elements; t++)
                    bf[j].x[t] = wmma::__float_to_tf32(bf[j].x[t]);
            }
            #pragma unroll
            for (int i = 0; i < 4; i++)
                #pragma unroll
                for (int j = 0; j < 4; j++)
                    wmma::mma_sync(c[i][j], af[i], bf[j], c[i][j]);
        }
        __syncthreads();
    }

    float* sC = sm;  // [128][260], reuses full dynamic buffer
    #pragma unroll
    for (int i = 0; i < 4; i++)
        #pragma unroll
        for (int j = 0; j < 4; j++)
            wmma::store_matrix_sync(sC + (size_t)(wm * 64 + i * 16) * 260 + wn * 64 + j * 16,
                                    c[i][j], 260, wmma::mem_row_major);
    __syncthreads();

    const int b0 = blockIdx.y * 4;   // m = b_local*32 + c
    const int d0 = blockIdx.x * 8;   // n = d_local*32 + e
    #pragma unroll
    for (int it = 0; it < 32; it++) {
        int flat = tid + it * 256;           // 8192 float4s
        int n4 = flat & 63, m = flat >> 6;
        int di = n4 >> 3, e4 = (n4 & 7) << 2;
        float4 v = *(float4*)(sC + m * 260 + di * 32 + e4);
        size_t row = (size_t)(b0 + (m >> 5)) * NR + d0 + di;
        *(float4*)(g_inter + row * 1024 + ((m & 31) << 5) + e4) = v;
    }
}

// ---------------- Kernel 4: out = (inter*rinv) @ W + ob*rinv ---------------
__global__ __launch_bounds__(256) void gemm2_kernel(
    const float* __restrict__ ow, const float* __restrict__ ob,
    float* __restrict__ out)
{
    __shared__ float sA[128 * 36];
    __shared__ float sB[32 * 132];
    const int tid  = threadIdx.x;
    const int warp = tid >> 5;
    const int wm = warp & 3, wn = warp >> 2;   // 4x2 warp grid of 32x64 slabs
    const int r0 = blockIdx.x * 128;

    wmma::fragment<wmma::accumulator, 16, 16, 8, float> c[2][4];
    #pragma unroll
    for (int i = 0; i < 2; i++)
        #pragma unroll
        for (int j = 0; j < 4; j++) wmma::fill_fragment(c[i][j], 0.0f);

    for (int k0 = 0; k0 < 1024; k0 += 32) {
        #pragma unroll
        for (int i = 0; i < 4; i++) {
            int idx = tid + i * 256;                    // 1024 float4s
            int m = idx >> 3, k4 = (idx & 7) << 2;
            float rv = g_rinv[r0 + m];
            float4 v = *(const float4*)(g_inter + (size_t)(r0 + m) * 1024 + k0 + k4);
            v.x *= rv; v.y *= rv; v.z *= rv; v.w *= rv;
            *(float4*)(sA + m * 36 + k4) = v;
        }
        #pragma unroll
        for (int i = 0; i < 4; i++) {
            int idx = tid + i * 256;
            int kk = idx >> 5, f4 = (idx & 31) << 2;
            *(float4*)(sB + kk * 132 + f4) = *(const float4*)(ow + (size_t)(k0 + kk) * 128 + f4);
        }
        __syncthreads();
        #pragma unroll
        for (int kk = 0; kk < 32; kk += 8) {
            wmma::fragment<wmma::matrix_a, 16, 16, 8, wmma::precision::tf32, wmma::row_major> af[2];
            wmma::fragment<wmma::matrix_b, 16, 16, 8, wmma::precision::tf32, wmma::row_major> bf[4];
            #pragma unroll
            for (int i = 0; i < 2; i++) {
                wmma::load_matrix_sync(af[i], sA + (wm * 32 + i * 16) * 36 + kk, 36);
                #pragma unroll
                for (int t = 0; t < af[i].num_elements; t++)
                    af[i].x[t] = wmma::__float_to_tf32(af[i].x[t]);
            }
            #pragma unroll
            for (int j = 0; j < 4; j++) {
                wmma::load_matrix_sync(bf[j], sB + kk * 132 + wn * 64 + j * 16, 132);
                #pragma unroll
                for (int t = 0; t < bf[j].num_elements; t++)
                    bf[j].x[t] = wmma::__float_to_tf32(bf[j].x[t]);
            }
            #pragma unroll
            for (int i = 0; i < 2; i++)
                #pragma unroll
                for (int j = 0; j < 4; j++)
                    wmma::mma_sync(c[i][j], af[i], bf[j], c[i][j]);
        }
        __syncthreads();
    }

    // rank-1 bias chunk: A[:,0]=rinv, B[0,:]=ob (handles output_b exactly)
    {
        int idx = tid;                       // fill sA rows, 1024 entries over 4 iters
        #pragma unroll
        for (int i = 0; i < 4; i++) {
            int id2 = idx + i * 256;
            int m = id2 >> 3, kk = id2 & 7;
            sA[m * 36 + kk] = (kk == 0) ? g_rinv[r0 + m] : 0.f;
        }
        #pragma unroll
        for (int i = 0; i < 4; i++) {
            int id2 = idx + i * 256;
            int kk = id2 >> 7, f = id2 & 127;
            sB[kk * 132 + f] = (kk == 0) ? ob[f] : 0.f;
        }
        __syncthreads();
        wmma::fragment<wmma::matrix_a, 16, 16, 8, wmma::precision::tf32, wmma::row_major> af[2];
        wmma::fragment<wmma::matrix_b, 16, 16, 8, wmma::precision::tf32, wmma::row_major> bf[4];
        #pragma unroll
        for (int i = 0; i < 2; i++) {
            wmma::load_matrix_sync(af[i], sA + (wm * 32 + i * 16) * 36, 36);
            #pragma unroll
            for (int t = 0; t < af[i].num_elements; t++)
                af[i].x[t] = wmma::__float_to_tf32(af[i].x[t]);
        }
        #pragma unroll
        for (int j = 0; j < 4; j++) {
            wmma::load_matrix_sync(bf[j], sB + wn * 64 + j * 16, 132);
            #pragma unroll
            for (int t = 0; t < bf[j].num_elements; t++)
                bf[j].x[t] = wmma::__float_to_tf32(bf[j].x[t]);
        }
        #pragma unroll
        for (int i = 0; i < 2; i++)
            #pragma unroll
            for (int j = 0; j < 4; j++)
                wmma::mma_sync(c[i][j], af[i], bf[j], c[i][j]);
    }

    #pragma unroll
    for (int i = 0; i < 2; i++)
        #pragma unroll
        for (int j = 0; j < 4; j++)
            wmma::store_matrix_sync(out + (size_t)(r0 + wm * 32 + i * 16) * 128 + wn * 64 + j * 16,
                                    c[i][j], 128, wmma::mem_row_major);
}

// ---------------------------------------------------------------------------
extern "C" void kernel_launch(void* const* d_in, const int* in_sizes, int n_in,
                              void* d_out, int out_size)
{
    const float* act      = (const float*)d_in[0];
    const float* mask     = (const float*)d_in[1];
    const float* ln_scale = (const float*)d_in[2];
    const float* ln_off   = (const float*)d_in[3];
    const float* left_w   = (const float*)d_in[4];
    const float* left_b   = (const float*)d_in[5];
    const float* right_w  = (const float*)d_in[6];
    const float* right_b  = (const float*)d_in[7];
    const float* out_w    = (const float*)d_in[8];
    const float* out_b    = (const float*)d_in[9];
    float* out = (float*)d_out;

    const int smem1 = (64 * 260 + 256 * 64 + 64) * 4;       // 132352
    const int smem3 = 128 * 260 * 4;                        // 133120
    cudaFuncSetAttribute(ln_proj_kernel, cudaFuncAttributeMaxDynamicSharedMemorySize, smem1);
    cudaFuncSetAttribute(gemm1_kernel,   cudaFuncAttributeMaxDynamicSharedMemorySize, smem3);

    ln_proj_kernel<<<(NS * NR) / 64, 256, smem1>>>(act, mask, ln_scale, ln_off,
                                                   left_w, left_b, right_w, right_b);
    norm_kernel<<<NR, NR>>>(mask);
    gemm1_kernel<<<dim3(MT / 256, MT / 128), 256, smem3>>>();
    gemm2_kernel<<<RT / 128, 256>>>(out_w, out_b, out);
}